// round 6
// baseline (speedup 1.0000x reference)
#include <cuda_runtime.h>
#include <cuda_bf16.h>
#include <cstdint>

#define NTOK 16384
#define HD   2048
#define NE   8
#define BD   128
#define EPSF 1e-6f

// ---------------- static device scratch ----------------
__device__ __nv_bfloat16 g_xb [NTOK * HD];
__device__ __nv_bfloat16 g_w1b[NE * BD * HD];
__device__ __nv_bfloat16 g_w2b[NE * HD * BD];
__device__ __nv_bfloat16 g_h  [NE * NTOK * BD];
__device__ __nv_bfloat16 g_scr[2 * NTOK * HD];
__device__ float g_w   [NTOK * NE];
__device__ float g_prob[NTOK * NE];
__device__ int   g_tok [NE * NTOK];
__device__ int   g_cnt [NE];

// ---------------- helpers ----------------
static __device__ __forceinline__ uint32_t smem_u32(const void* p) {
    return (uint32_t)__cvta_generic_to_shared(p);
}
#define CP16(dst_u32, src_ptr) \
    asm volatile("cp.async.cg.shared.global [%0], [%1], 16;\n" :: "r"(dst_u32), "l"(src_ptr))
#define CP_COMMIT() asm volatile("cp.async.commit_group;\n" ::)
#define CP_WAIT(n)  asm volatile("cp.async.wait_group %0;\n" :: "n"(n))

static __device__ __forceinline__ void ldm4(uint32_t& r0, uint32_t& r1, uint32_t& r2, uint32_t& r3,
                                            uint32_t addr) {
    asm volatile("ldmatrix.sync.aligned.m8n8.x4.shared.b16 {%0,%1,%2,%3}, [%4];"
                 : "=r"(r0), "=r"(r1), "=r"(r2), "=r"(r3) : "r"(addr));
}
static __device__ __forceinline__ void mma16816(float* c, const uint32_t* a, const uint32_t* b) {
    asm volatile(
        "mma.sync.aligned.m16n8k16.row.col.f32.bf16.bf16.f32 "
        "{%0,%1,%2,%3}, {%4,%5,%6,%7}, {%8,%9}, {%0,%1,%2,%3};"
        : "+f"(c[0]), "+f"(c[1]), "+f"(c[2]), "+f"(c[3])
        : "r"(a[0]), "r"(a[1]), "r"(a[2]), "r"(a[3]), "r"(b[0]), "r"(b[1]));
}

// ---------------- kernel 1: weights -> bf16 (+ counter init) ----------------
__global__ void k_convert(const float* __restrict__ W1, const float* __restrict__ W2) {
    if (blockIdx.x == 0 && threadIdx.x < NE) g_cnt[threadIdx.x] = 0;
    int total = NE * BD * HD;
    for (int i = blockIdx.x * blockDim.x + threadIdx.x; i < total; i += gridDim.x * blockDim.x) {
        g_w1b[i] = __float2bfloat16(W1[i]);
        g_w2b[i] = __float2bfloat16(W2[i]);
    }
}

// ---------------- kernel 2: router (8 tokens per block, 8 warps = 8 experts) ----------------
#define RT 8
__global__ __launch_bounds__(256) void k_router(const float* __restrict__ x,
                                                const float* __restrict__ skin,
                                                const float* __restrict__ Wimg,
                                                const float* __restrict__ Wskin) {
    int nb = blockIdx.x * RT;
    int tid = threadIdx.x, lane = tid & 31, wid = tid >> 5;

    __shared__ float lg[RT][NE];

    const float4* wr = (const float4*)(Wimg + (size_t)wid * HD);
#pragma unroll
    for (int t = 0; t < RT; t++) {
        int n = nb + t;
        const float4* xr = (const float4*)(x + (size_t)n * HD);
        float acc = 0.f;
#pragma unroll 4
        for (int j = lane; j < HD / 4; j += 32) {
            float4 a = xr[j];
            float4 b = wr[j];
            acc += a.x * b.x + a.y * b.y + a.z * b.z + a.w * b.w;
        }
#pragma unroll
        for (int o = 16; o; o >>= 1) acc += __shfl_xor_sync(0xffffffffu, acc, o);
        if (lane == 0) {
            float s = skin[n * 3 + 0] * Wskin[wid * 3 + 0] +
                      skin[n * 3 + 1] * Wskin[wid * 3 + 1] +
                      skin[n * 3 + 2] * Wskin[wid * 3 + 2];
            lg[t][wid] = acc + s;
        }
    }

    {
        const float4* xs = (const float4*)(x + (size_t)nb * HD);
        __nv_bfloat162* xd = (__nv_bfloat162*)(g_xb + (size_t)nb * HD);
        for (int i = tid; i < RT * HD / 4; i += 256) {
            float4 a = xs[i];
            __nv_bfloat162 p0, p1;
            p0.x = __float2bfloat16(a.x); p0.y = __float2bfloat16(a.y);
            p1.x = __float2bfloat16(a.z); p1.y = __float2bfloat16(a.w);
            xd[2 * i] = p0; xd[2 * i + 1] = p1;
        }
    }
    __syncthreads();

    if (tid < RT) {
        int t = tid, n = nb + t;
        float p[NE];
        float mx = lg[t][0];
#pragma unroll
        for (int e = 1; e < NE; e++) mx = fmaxf(mx, lg[t][e]);
        float ssum = 0.f;
#pragma unroll
        for (int e = 0; e < NE; e++) { p[e] = expf(lg[t][e] - mx); ssum += p[e]; }
        float inv = 1.f / ssum;
#pragma unroll
        for (int e = 0; e < NE; e++) p[e] *= inv;

        int i1 = 0;
#pragma unroll
        for (int e = 1; e < NE; e++) if (p[e] > p[i1]) i1 = e;
        int i2 = (i1 == 0) ? 1 : 0;
#pragma unroll
        for (int e = 0; e < NE; e++) { if (e != i1 && p[e] > p[i2]) i2 = e; }

        float v1 = p[i1], v2 = p[i2];
        float wn = 1.f / (v1 + v2 + EPSF);
        float wv[NE];
#pragma unroll
        for (int e = 0; e < NE; e++) wv[e] = 0.f;
        wv[i1] = v1 * wn;
        wv[i2] = v2 * wn;
#pragma unroll
        for (int e = 0; e < NE; e++) { g_w[n * NE + e] = wv[e]; g_prob[n * NE + e] = p[e]; }

        int p1 = atomicAdd(&g_cnt[i1], 1); g_tok[i1 * NTOK + p1] = n * 2 + 0;
        int p2 = atomicAdd(&g_cnt[i2], 1); g_tok[i2 * NTOK + p2] = n * 2 + 1;
    }
}

// ---------------- kernel 3: GEMM1  h = relu(Xg @ W1^T + b1) ----------------
// tile M=64 x N=128, K-stage 64, 2 stages
#define G1_SMEM ((2 * 64 * 72 + 2 * 128 * 72) * 2)
__global__ __launch_bounds__(256) void k_gemm1(const float* __restrict__ b1) {
    extern __shared__ __align__(16) char smraw1[];
    __nv_bfloat16 (*As)[64][72]  = (__nv_bfloat16 (*)[64][72])smraw1;
    __nv_bfloat16 (*Bs)[128][72] = (__nv_bfloat16 (*)[128][72])(smraw1 + 2 * 64 * 72 * 2);

    int e = blockIdx.z;
    int cnt = g_cnt[e];
    int m0 = blockIdx.y * 64;
    if (m0 >= cnt) return;

    int tid = threadIdx.x, lane = tid & 31, wid = tid >> 5;
    int wm = wid >> 1, wn = wid & 1;   // warp tile 16(M) x 64(N)

    int rA = tid >> 2;                 // 0..63  (A row; 2 chunks each)
    int rB = tid >> 1;                 // 0..127 (B row; 4 chunks each)
    int tokr = (m0 + rA < cnt) ? (g_tok[e * NTOK + m0 + rA] >> 1) : 0;

    float c[8][4];
#pragma unroll
    for (int ni = 0; ni < 8; ni++)
#pragma unroll
        for (int q = 0; q < 4; q++) c[ni][q] = 0.f;

    const int NKK = HD / 64;  // 32

#define G1_LOAD(s, k0)                                                                          \
    do {                                                                                        \
        _Pragma("unroll")                                                                       \
        for (int q = 0; q < 2; q++) {                                                           \
            int col = ((tid & 3) + q * 4) * 8;                                                  \
            CP16(smem_u32(&As[s][rA][col]), g_xb + (size_t)tokr * HD + (k0) + col);             \
        }                                                                                       \
        _Pragma("unroll")                                                                       \
        for (int q = 0; q < 4; q++) {                                                           \
            int col = ((tid & 1) * 4 + q) * 8;                                                  \
            CP16(smem_u32(&Bs[s][rB][col]), g_w1b + ((size_t)e * BD + rB) * HD + (k0) + col);   \
        }                                                                                       \
    } while (0)

    G1_LOAD(0, 0);
    CP_COMMIT();

    for (int it = 0; it < NKK; it++) {
        CP_WAIT(0);
        __syncthreads();
        if (it + 1 < NKK) { G1_LOAD((it + 1) & 1, (it + 1) * 64); CP_COMMIT(); }

        int s = it & 1;
#pragma unroll
        for (int kk = 0; kk < 4; kk++) {
            uint32_t a[4];
            {
                uint32_t ad = smem_u32(&As[s][wm * 16 + (lane & 15)][kk * 16 + ((lane >> 4) << 3)]);
                ldm4(a[0], a[1], a[2], a[3], ad);
            }
            uint32_t b[8][2];
#pragma unroll
            for (int nj = 0; nj < 4; nj++) {
                uint32_t ad = smem_u32(&Bs[s][wn * 64 + nj * 16 + (lane & 7) + ((lane >> 4) << 3)]
                                          [kk * 16 + (((lane >> 3) & 1) << 3)]);
                uint32_t r0, r1, r2, r3;
                ldm4(r0, r1, r2, r3, ad);
                b[2 * nj][0] = r0; b[2 * nj][1] = r1;
                b[2 * nj + 1][0] = r2; b[2 * nj + 1][1] = r3;
            }
#pragma unroll
            for (int ni = 0; ni < 8; ni++) mma16816(c[ni], a, b[ni]);
        }
    }

    const float* b1e = b1 + e * BD;
#pragma unroll
    for (int rr = 0; rr < 2; rr++) {
        int gr = m0 + wm * 16 + (lane >> 2) + rr * 8;
        if (gr < cnt) {
            __nv_bfloat16* hp = g_h + ((size_t)e * NTOK + gr) * BD;
#pragma unroll
            for (int ni = 0; ni < 8; ni++) {
                int col = wn * 64 + ni * 8 + (lane & 3) * 2;
                float v0 = fmaxf(c[ni][rr * 2 + 0] + b1e[col], 0.f);
                float v1 = fmaxf(c[ni][rr * 2 + 1] + b1e[col + 1], 0.f);
                __nv_bfloat162 pk;
                pk.x = __float2bfloat16(v0);
                pk.y = __float2bfloat16(v1);
                *(__nv_bfloat162*)(hp + col) = pk;
            }
        }
    }
}

// ---------------- kernel 4: GEMM2 one tile per CTA ----------------
#define G2_SMEM (2 * 128 * 136 * 2)
__global__ __launch_bounds__(256) void k_gemm2(const float* __restrict__ b2) {
    extern __shared__ __align__(16) char smraw2[];
    __nv_bfloat16 (*As)[136] = (__nv_bfloat16 (*)[136])smraw2;
    __nv_bfloat16 (*Bs)[136] = (__nv_bfloat16 (*)[136])(smraw2 + 128 * 136 * 2);

    __shared__ int   vrow[128];
    __shared__ float wrow[128];
    __shared__ float b2s[128];

    int e = blockIdx.y;
    int n0 = blockIdx.x * 128;
    int cnt = g_cnt[e];
    int m0 = blockIdx.z * 128;
    if (m0 >= cnt) return;

    int tid = threadIdx.x, lane = tid & 31, wid = tid >> 5;
    int wm = wid >> 1, wn = wid & 1;

    // load A and B tiles (single batch): row = tid>>1, 8 chunks each
    {
        int r = tid >> 1;
#pragma unroll
        for (int q = 0; q < 8; q++) {
            int col = ((tid & 1) * 8 + q) * 8;
            CP16(smem_u32(&As[r][col]), g_h + ((size_t)e * NTOK + m0 + r) * BD + col);
            CP16(smem_u32(&Bs[r][col]), g_w2b + ((size_t)e * HD + n0 + r) * BD + col);
        }
    }
    CP_COMMIT();

    if (tid < 128) {
        int gr = m0 + tid;
        int v = (gr < cnt) ? g_tok[e * NTOK + gr] : 0;
        vrow[tid] = v;
        wrow[tid] = (gr < cnt) ? g_w[(v >> 1) * NE + e] : 0.f;
        b2s[tid] = b2[(size_t)e * HD + n0 + tid];
    }

    float c[2][8][4];
#pragma unroll
    for (int mi = 0; mi < 2; mi++)
#pragma unroll
        for (int ni = 0; ni < 8; ni++)
#pragma unroll
            for (int q = 0; q < 4; q++) c[mi][ni][q] = 0.f;

    CP_WAIT(0);
    __syncthreads();

#pragma unroll
    for (int kk = 0; kk < 8; kk++) {
        uint32_t a[2][4];
#pragma unroll
        for (int mi = 0; mi < 2; mi++) {
            uint32_t ad = smem_u32(&As[wm * 32 + mi * 16 + (lane & 15)][kk * 16 + ((lane >> 4) << 3)]);
            ldm4(a[mi][0], a[mi][1], a[mi][2], a[mi][3], ad);
        }
        uint32_t b[8][2];
#pragma unroll
        for (int nj = 0; nj < 4; nj++) {
            uint32_t ad = smem_u32(&Bs[wn * 64 + nj * 16 + (lane & 7) + ((lane >> 4) << 3)]
                                      [kk * 16 + (((lane >> 3) & 1) << 3)]);
            uint32_t r0, r1, r2, r3;
            ldm4(r0, r1, r2, r3, ad);
            b[2 * nj][0] = r0; b[2 * nj][1] = r1;
            b[2 * nj + 1][0] = r2; b[2 * nj + 1][1] = r3;
        }
#pragma unroll
        for (int mi = 0; mi < 2; mi++)
#pragma unroll
            for (int ni = 0; ni < 8; ni++) mma16816(c[mi][ni], a[mi], b[ni]);
    }

    // stage scaled C into As (done reading it)
    __syncthreads();
#pragma unroll
    for (int mi = 0; mi < 2; mi++) {
#pragma unroll
        for (int rr = 0; rr < 2; rr++) {
            int lr = wm * 32 + mi * 16 + (lane >> 2) + rr * 8;
            float wv = wrow[lr];
#pragma unroll
            for (int ni = 0; ni < 8; ni++) {
                int col = wn * 64 + ni * 8 + (lane & 3) * 2;
                float v0 = wv * (c[mi][ni][rr * 2 + 0] + b2s[col]);
                float v1 = wv * (c[mi][ni][rr * 2 + 1] + b2s[col + 1]);
                __nv_bfloat162 pk;
                pk.x = __float2bfloat16(v0);
                pk.y = __float2bfloat16(v1);
                *(__nv_bfloat162*)(&As[lr][col]) = pk;
            }
        }
    }
    __syncthreads();

    // coalesced scatter store: 16 lanes per 256B row segment
    int lim = cnt - m0;
    for (int i = tid; i < 2048; i += 256) {
        int r = i >> 4, cc = (i & 15) << 3;
        if (r < lim) {
            int v = vrow[r];
            uint4 val = *(const uint4*)(&As[r][cc]);
            *(uint4*)(g_scr + (size_t)v * HD + n0 + cc) = val;
        }
    }
}

// ---------------- kernel 5: combine ----------------
__global__ __launch_bounds__(256) void k_combine(const float* __restrict__ x, float* __restrict__ out) {
    int n = blockIdx.x;
    int tid = threadIdx.x;
    const float4* xr = (const float4*)(x + (size_t)n * HD);
    float4* o = (float4*)(out + (size_t)n * HD);
    const __nv_bfloat162* s0 = (const __nv_bfloat162*)(g_scr + (size_t)(2 * n) * HD);
    const __nv_bfloat162* s1 = (const __nv_bfloat162*)(g_scr + (size_t)(2 * n + 1) * HD);
#pragma unroll
    for (int j = tid; j < HD / 4; j += 256) {
        float4 a = xr[j];
        __nv_bfloat162 p0 = s0[2 * j], p1 = s0[2 * j + 1];
        __nv_bfloat162 q0 = s1[2 * j], q1 = s1[2 * j + 1];
        float4 r;
        r.x = a.x + __bfloat162float(p0.x) + __bfloat162float(q0.x);
        r.y = a.y + __bfloat162float(p0.y) + __bfloat162float(q0.y);
        r.z = a.z + __bfloat162float(p1.x) + __bfloat162float(q1.x);
        r.w = a.w + __bfloat162float(p1.y) + __bfloat162float(q1.y);
        o[j] = r;
    }
}

// ---------------- kernel 6: aux loss ----------------
__global__ void k_aux(float* __restrict__ out, int out_size) {
    if (out_size <= NTOK * HD) return;
    __shared__ float red[256];
    __shared__ float auxs;
    int tid = threadIdx.x;
    if (tid == 0) auxs = 0.f;
    float acc[NE];
#pragma unroll
    for (int e = 0; e < NE; e++) acc[e] = 0.f;
    for (int n = tid; n < NTOK; n += 256) {
#pragma unroll
        for (int e = 0; e < NE; e++) acc[e] += g_prob[n * NE + e];
    }
    __syncthreads();
    for (int e = 0; e < NE; e++) {
        red[tid] = acc[e];
        __syncthreads();
        for (int s = 128; s > 0; s >>= 1) {
            if (tid < s) red[tid] += red[tid + s];
            __syncthreads();
        }
        if (tid == 0) {
            float mp = red[0] / (float)NTOK;
            float mf = (float)g_cnt[e] / (float)NTOK;
            auxs += mp * mf;
        }
        __syncthreads();
    }
    if (tid == 0) out[(size_t)NTOK * HD] = auxs * (float)NE;
}

// ---------------- launch ----------------
extern "C" void kernel_launch(void* const* d_in, const int* in_sizes, int n_in,
                              void* d_out, int out_size) {
    const float* x     = (const float*)d_in[0];
    const float* skin  = (const float*)d_in[1];
    const float* Wimg  = (const float*)d_in[2];
    const float* Wskin = (const float*)d_in[3];
    const float* W1    = (const float*)d_in[4];
    const float* b1    = (const float*)d_in[5];
    const float* W2    = (const float*)d_in[6];
    const float* b2    = (const float*)d_in[7];
    float* out = (float*)d_out;

    cudaFuncSetAttribute(k_gemm1, cudaFuncAttributeMaxDynamicSharedMemorySize, G1_SMEM);
    cudaFuncSetAttribute(k_gemm2, cudaFuncAttributeMaxDynamicSharedMemorySize, G2_SMEM);

    k_convert<<<2048, 256>>>(W1, W2);
    k_router<<<NTOK / RT, 256>>>(x, skin, Wimg, Wskin);
    k_gemm1<<<dim3(1, NTOK / 64, NE), 256, G1_SMEM>>>(b1);
    k_gemm2<<<dim3(HD / 128, NE, NTOK / 128), 256, G2_SMEM>>>(b2);
    k_combine<<<NTOK, 256>>>(x, out);
    k_aux<<<1, 256>>>(out, out_size);
}

// round 7
// speedup vs baseline: 1.1042x; 1.1042x over previous
#include <cuda_runtime.h>
#include <cuda_bf16.h>
#include <cstdint>

#define NTOK 16384
#define HD   2048
#define NE   8
#define BD   128
#define EPSF 1e-6f

// ---------------- static device scratch ----------------
__device__ __nv_bfloat16 g_xb [NTOK * HD];
__device__ __nv_bfloat16 g_w1b[NE * BD * HD];
__device__ __nv_bfloat16 g_w2b[NE * HD * BD];
__device__ __nv_bfloat16 g_h  [NE * NTOK * BD];
__device__ __nv_bfloat16 g_scr[2 * NTOK * HD];
__device__ float g_w   [NTOK * NE];
__device__ float g_prob[NTOK * NE];
__device__ int   g_tok [NE * NTOK];
__device__ int   g_cnt [NE];

// ---------------- helpers ----------------
static __device__ __forceinline__ uint32_t smem_u32(const void* p) {
    return (uint32_t)__cvta_generic_to_shared(p);
}
#define CP16(dst_u32, src_ptr) \
    asm volatile("cp.async.cg.shared.global [%0], [%1], 16;\n" :: "r"(dst_u32), "l"(src_ptr))
#define CP_COMMIT() asm volatile("cp.async.commit_group;\n" ::)
#define CP_WAIT(n)  asm volatile("cp.async.wait_group %0;\n" :: "n"(n))

static __device__ __forceinline__ void ldm4(uint32_t& r0, uint32_t& r1, uint32_t& r2, uint32_t& r3,
                                            uint32_t addr) {
    asm volatile("ldmatrix.sync.aligned.m8n8.x4.shared.b16 {%0,%1,%2,%3}, [%4];"
                 : "=r"(r0), "=r"(r1), "=r"(r2), "=r"(r3) : "r"(addr));
}
static __device__ __forceinline__ void mma16816(float* c, const uint32_t* a, const uint32_t* b) {
    asm volatile(
        "mma.sync.aligned.m16n8k16.row.col.f32.bf16.bf16.f32 "
        "{%0,%1,%2,%3}, {%4,%5,%6,%7}, {%8,%9}, {%0,%1,%2,%3};"
        : "+f"(c[0]), "+f"(c[1]), "+f"(c[2]), "+f"(c[3])
        : "r"(a[0]), "r"(a[1]), "r"(a[2]), "r"(a[3]), "r"(b[0]), "r"(b[1]));
}

// ---------------- kernel 1: weights -> bf16 (+ counter init) ----------------
__global__ void k_convert(const float* __restrict__ W1, const float* __restrict__ W2) {
    if (blockIdx.x == 0 && threadIdx.x < NE) g_cnt[threadIdx.x] = 0;
    int total = NE * BD * HD;
    for (int i = blockIdx.x * blockDim.x + threadIdx.x; i < total; i += gridDim.x * blockDim.x) {
        g_w1b[i] = __float2bfloat16(W1[i]);
        g_w2b[i] = __float2bfloat16(W2[i]);
    }
}

// ---------------- kernel 2: router (8 tokens per block, 8 warps = 8 experts) ----------------
#define RT 8
__global__ __launch_bounds__(256) void k_router(const float* __restrict__ x,
                                                const float* __restrict__ skin,
                                                const float* __restrict__ Wimg,
                                                const float* __restrict__ Wskin) {
    int nb = blockIdx.x * RT;
    int tid = threadIdx.x, lane = tid & 31, wid = tid >> 5;

    __shared__ float lg[RT][NE];

    const float4* wr = (const float4*)(Wimg + (size_t)wid * HD);
#pragma unroll
    for (int t = 0; t < RT; t++) {
        int n = nb + t;
        const float4* xr = (const float4*)(x + (size_t)n * HD);
        float acc = 0.f;
#pragma unroll 4
        for (int j = lane; j < HD / 4; j += 32) {
            float4 a = xr[j];
            float4 b = wr[j];
            acc += a.x * b.x + a.y * b.y + a.z * b.z + a.w * b.w;
        }
#pragma unroll
        for (int o = 16; o; o >>= 1) acc += __shfl_xor_sync(0xffffffffu, acc, o);
        if (lane == 0) {
            float s = skin[n * 3 + 0] * Wskin[wid * 3 + 0] +
                      skin[n * 3 + 1] * Wskin[wid * 3 + 1] +
                      skin[n * 3 + 2] * Wskin[wid * 3 + 2];
            lg[t][wid] = acc + s;
        }
    }

    {
        const float4* xs = (const float4*)(x + (size_t)nb * HD);
        __nv_bfloat162* xd = (__nv_bfloat162*)(g_xb + (size_t)nb * HD);
        for (int i = tid; i < RT * HD / 4; i += 256) {
            float4 a = xs[i];
            __nv_bfloat162 p0, p1;
            p0.x = __float2bfloat16(a.x); p0.y = __float2bfloat16(a.y);
            p1.x = __float2bfloat16(a.z); p1.y = __float2bfloat16(a.w);
            xd[2 * i] = p0; xd[2 * i + 1] = p1;
        }
    }
    __syncthreads();

    if (tid < RT) {
        int t = tid, n = nb + t;
        float p[NE];
        float mx = lg[t][0];
#pragma unroll
        for (int e = 1; e < NE; e++) mx = fmaxf(mx, lg[t][e]);
        float ssum = 0.f;
#pragma unroll
        for (int e = 0; e < NE; e++) { p[e] = expf(lg[t][e] - mx); ssum += p[e]; }
        float inv = 1.f / ssum;
#pragma unroll
        for (int e = 0; e < NE; e++) p[e] *= inv;

        int i1 = 0;
#pragma unroll
        for (int e = 1; e < NE; e++) if (p[e] > p[i1]) i1 = e;
        int i2 = (i1 == 0) ? 1 : 0;
#pragma unroll
        for (int e = 0; e < NE; e++) { if (e != i1 && p[e] > p[i2]) i2 = e; }

        float v1 = p[i1], v2 = p[i2];
        float wn = 1.f / (v1 + v2 + EPSF);
        float wv[NE];
#pragma unroll
        for (int e = 0; e < NE; e++) wv[e] = 0.f;
        wv[i1] = v1 * wn;
        wv[i2] = v2 * wn;
#pragma unroll
        for (int e = 0; e < NE; e++) { g_w[n * NE + e] = wv[e]; g_prob[n * NE + e] = p[e]; }

        int p1 = atomicAdd(&g_cnt[i1], 1); g_tok[i1 * NTOK + p1] = n * 2 + 0;
        int p2 = atomicAdd(&g_cnt[i2], 1); g_tok[i2 * NTOK + p2] = n * 2 + 1;
    }
}

// ---------------- kernel 3: GEMM1  h = relu(Xg @ W1^T + b1) ; 4-stage, 128x128 tile ----------------
#define G1_STAGES 4
#define G1_SMEM (G1_STAGES * 128 * 40 * 2 * 2)
__global__ __launch_bounds__(256) void k_gemm1(const float* __restrict__ b1) {
    extern __shared__ __align__(16) char smraw1[];
    __nv_bfloat16 (*As)[128][40] = (__nv_bfloat16 (*)[128][40])smraw1;
    __nv_bfloat16 (*Bs)[128][40] =
        (__nv_bfloat16 (*)[128][40])(smraw1 + G1_STAGES * 128 * 40 * 2);

    int e = blockIdx.z;
    int cnt = g_cnt[e];
    int m0 = blockIdx.y * 128;
    if (m0 >= cnt) return;

    int tid = threadIdx.x, lane = tid & 31, wid = tid >> 5;
    int wm = wid >> 1, wn = wid & 1;

    int rA0 = tid >> 2, rA1 = 64 + (tid >> 2), ch = tid & 3;
    int tok0 = (m0 + rA0 < cnt) ? (g_tok[e * NTOK + m0 + rA0] >> 1) : 0;
    int tok1 = (m0 + rA1 < cnt) ? (g_tok[e * NTOK + m0 + rA1] >> 1) : 0;

    float c[2][8][4];
#pragma unroll
    for (int mi = 0; mi < 2; mi++)
#pragma unroll
        for (int ni = 0; ni < 8; ni++)
#pragma unroll
            for (int q = 0; q < 4; q++) c[mi][ni][q] = 0.f;

    const int NK = HD / 32;  // 64

#define G1_LOAD(s, k0)                                                                        \
    do {                                                                                      \
        CP16(smem_u32(&As[s][rA0][ch * 8]), g_xb + (size_t)tok0 * HD + (k0) + ch * 8);        \
        CP16(smem_u32(&As[s][rA1][ch * 8]), g_xb + (size_t)tok1 * HD + (k0) + ch * 8);        \
        CP16(smem_u32(&Bs[s][rA0][ch * 8]), g_w1b + ((size_t)e * BD + rA0) * HD + (k0) + ch * 8); \
        CP16(smem_u32(&Bs[s][rA1][ch * 8]), g_w1b + ((size_t)e * BD + rA1) * HD + (k0) + ch * 8); \
    } while (0)

#pragma unroll
    for (int s = 0; s < G1_STAGES - 1; s++) { G1_LOAD(s, s * 32); CP_COMMIT(); }

    for (int it = 0; it < NK; it++) {
        CP_WAIT(G1_STAGES - 2);
        __syncthreads();
        int pf = it + G1_STAGES - 1;
        if (pf < NK) G1_LOAD(pf & (G1_STAGES - 1), pf * 32);
        CP_COMMIT();

        int s = it & (G1_STAGES - 1);
#pragma unroll
        for (int kk = 0; kk < 2; kk++) {
            uint32_t a[2][4];
#pragma unroll
            for (int mi = 0; mi < 2; mi++) {
                uint32_t ad = smem_u32(&As[s][wm * 32 + mi * 16 + (lane & 15)][kk * 16 + ((lane >> 4) << 3)]);
                ldm4(a[mi][0], a[mi][1], a[mi][2], a[mi][3], ad);
            }
            uint32_t b[8][2];
#pragma unroll
            for (int nj = 0; nj < 4; nj++) {
                uint32_t ad = smem_u32(&Bs[s][wn * 64 + nj * 16 + (lane & 7) + ((lane >> 4) << 3)]
                                          [kk * 16 + (((lane >> 3) & 1) << 3)]);
                uint32_t r0, r1, r2, r3;
                ldm4(r0, r1, r2, r3, ad);
                b[2 * nj][0] = r0; b[2 * nj][1] = r1;
                b[2 * nj + 1][0] = r2; b[2 * nj + 1][1] = r3;
            }
#pragma unroll
            for (int mi = 0; mi < 2; mi++)
#pragma unroll
                for (int ni = 0; ni < 8; ni++) mma16816(c[mi][ni], a[mi], b[ni]);
        }
    }

    const float* b1e = b1 + e * BD;
#pragma unroll
    for (int mi = 0; mi < 2; mi++) {
#pragma unroll
        for (int rr = 0; rr < 2; rr++) {
            int gr = m0 + wm * 32 + mi * 16 + (lane >> 2) + rr * 8;
            if (gr < cnt) {
                __nv_bfloat16* hp = g_h + ((size_t)e * NTOK + gr) * BD;
#pragma unroll
                for (int ni = 0; ni < 8; ni++) {
                    int col = wn * 64 + ni * 8 + (lane & 3) * 2;
                    float v0 = fmaxf(c[mi][ni][rr * 2 + 0] + b1e[col], 0.f);
                    float v1 = fmaxf(c[mi][ni][rr * 2 + 1] + b1e[col + 1], 0.f);
                    __nv_bfloat162 pk;
                    pk.x = __float2bfloat16(v0);
                    pk.y = __float2bfloat16(v1);
                    *(__nv_bfloat162*)(hp + col) = pk;
                }
            }
        }
    }
}

// ---------------- kernel 4: GEMM2 one tile per CTA, K split into 2 async groups ----------------
#define G2_SMEM (2 * 128 * 136 * 2)
__global__ __launch_bounds__(256) void k_gemm2(const float* __restrict__ b2) {
    extern __shared__ __align__(16) char smraw2[];
    __nv_bfloat16 (*As)[136] = (__nv_bfloat16 (*)[136])smraw2;
    __nv_bfloat16 (*Bs)[136] = (__nv_bfloat16 (*)[136])(smraw2 + 128 * 136 * 2);

    __shared__ int   vrow[128];
    __shared__ float wrow[128];
    __shared__ float b2s[128];

    int e = blockIdx.y;
    int n0 = blockIdx.x * 128;
    int cnt = g_cnt[e];
    int m0 = blockIdx.z * 128;
    if (m0 >= cnt) return;

    int tid = threadIdx.x, lane = tid & 31, wid = tid >> 5;
    int wm = wid >> 1, wn = wid & 1;

    int r = tid >> 1;
    const __nv_bfloat16* gA = g_h + ((size_t)e * NTOK + m0 + r) * BD;
    const __nv_bfloat16* gB = g_w2b + ((size_t)e * HD + n0 + r) * BD;

    // group 0: K columns 0..63
#pragma unroll
    for (int q = 0; q < 4; q++) {
        int col = ((tid & 1) * 4 + q) * 8;
        CP16(smem_u32(&As[r][col]), gA + col);
        CP16(smem_u32(&Bs[r][col]), gB + col);
    }
    CP_COMMIT();
    // group 1: K columns 64..127
#pragma unroll
    for (int q = 0; q < 4; q++) {
        int col = 64 + ((tid & 1) * 4 + q) * 8;
        CP16(smem_u32(&As[r][col]), gA + col);
        CP16(smem_u32(&Bs[r][col]), gB + col);
    }
    CP_COMMIT();

    if (tid < 128) {
        int gr = m0 + tid;
        int v = (gr < cnt) ? g_tok[e * NTOK + gr] : 0;
        vrow[tid] = v;
        wrow[tid] = (gr < cnt) ? g_w[(v >> 1) * NE + e] : 0.f;
        b2s[tid] = b2[(size_t)e * HD + n0 + tid];
    }

    float c[2][8][4];
#pragma unroll
    for (int mi = 0; mi < 2; mi++)
#pragma unroll
        for (int ni = 0; ni < 8; ni++)
#pragma unroll
            for (int q = 0; q < 4; q++) c[mi][ni][q] = 0.f;

    // first K-half ready
    CP_WAIT(1);
    __syncthreads();

#pragma unroll
    for (int half = 0; half < 2; half++) {
        if (half == 1) {
            CP_WAIT(0);
            __syncthreads();
        }
#pragma unroll
        for (int k4 = 0; k4 < 4; k4++) {
            int kk = half * 4 + k4;
            uint32_t a[2][4];
#pragma unroll
            for (int mi = 0; mi < 2; mi++) {
                uint32_t ad = smem_u32(&As[wm * 32 + mi * 16 + (lane & 15)][kk * 16 + ((lane >> 4) << 3)]);
                ldm4(a[mi][0], a[mi][1], a[mi][2], a[mi][3], ad);
            }
            uint32_t b[8][2];
#pragma unroll
            for (int nj = 0; nj < 4; nj++) {
                uint32_t ad = smem_u32(&Bs[wn * 64 + nj * 16 + (lane & 7) + ((lane >> 4) << 3)]
                                          [kk * 16 + (((lane >> 3) & 1) << 3)]);
                uint32_t r0, r1, r2, r3;
                ldm4(r0, r1, r2, r3, ad);
                b[2 * nj][0] = r0; b[2 * nj][1] = r1;
                b[2 * nj + 1][0] = r2; b[2 * nj + 1][1] = r3;
            }
#pragma unroll
            for (int mi = 0; mi < 2; mi++)
#pragma unroll
                for (int ni = 0; ni < 8; ni++) mma16816(c[mi][ni], a[mi], b[ni]);
        }
    }

    // stage scaled C into As (done reading it)
    __syncthreads();
#pragma unroll
    for (int mi = 0; mi < 2; mi++) {
#pragma unroll
        for (int rr = 0; rr < 2; rr++) {
            int lr = wm * 32 + mi * 16 + (lane >> 2) + rr * 8;
            float wv = wrow[lr];
#pragma unroll
            for (int ni = 0; ni < 8; ni++) {
                int col = wn * 64 + ni * 8 + (lane & 3) * 2;
                float v0 = wv * (c[mi][ni][rr * 2 + 0] + b2s[col]);
                float v1 = wv * (c[mi][ni][rr * 2 + 1] + b2s[col + 1]);
                __nv_bfloat162 pk;
                pk.x = __float2bfloat16(v0);
                pk.y = __float2bfloat16(v1);
                *(__nv_bfloat162*)(&As[lr][col]) = pk;
            }
        }
    }
    __syncthreads();

    // coalesced scatter store: 16 lanes per 256B row segment
    int lim = cnt - m0;
    for (int i = tid; i < 2048; i += 256) {
        int rr = i >> 4, cc = (i & 15) << 3;
        if (rr < lim) {
            int v = vrow[rr];
            uint4 val = *(const uint4*)(&As[rr][cc]);
            *(uint4*)(g_scr + (size_t)v * HD + n0 + cc) = val;
        }
    }
}

// ---------------- kernel 5: combine ----------------
__global__ __launch_bounds__(256) void k_combine(const float* __restrict__ x, float* __restrict__ out) {
    int n = blockIdx.x;
    int tid = threadIdx.x;
    const float4* xr = (const float4*)(x + (size_t)n * HD);
    float4* o = (float4*)(out + (size_t)n * HD);
    const __nv_bfloat162* s0 = (const __nv_bfloat162*)(g_scr + (size_t)(2 * n) * HD);
    const __nv_bfloat162* s1 = (const __nv_bfloat162*)(g_scr + (size_t)(2 * n + 1) * HD);
#pragma unroll
    for (int j = tid; j < HD / 4; j += 256) {
        float4 a = xr[j];
        __nv_bfloat162 p0 = s0[2 * j], p1 = s0[2 * j + 1];
        __nv_bfloat162 q0 = s1[2 * j], q1 = s1[2 * j + 1];
        float4 r;
        r.x = a.x + __bfloat162float(p0.x) + __bfloat162float(q0.x);
        r.y = a.y + __bfloat162float(p0.y) + __bfloat162float(q0.y);
        r.z = a.z + __bfloat162float(p1.x) + __bfloat162float(q1.x);
        r.w = a.w + __bfloat162float(p1.y) + __bfloat162float(q1.y);
        o[j] = r;
    }
}

// ---------------- kernel 6: aux loss ----------------
__global__ void k_aux(float* __restrict__ out, int out_size) {
    if (out_size <= NTOK * HD) return;
    __shared__ float red[256];
    __shared__ float auxs;
    int tid = threadIdx.x;
    if (tid == 0) auxs = 0.f;
    float acc[NE];
#pragma unroll
    for (int e = 0; e < NE; e++) acc[e] = 0.f;
    for (int n = tid; n < NTOK; n += 256) {
#pragma unroll
        for (int e = 0; e < NE; e++) acc[e] += g_prob[n * NE + e];
    }
    __syncthreads();
    for (int e = 0; e < NE; e++) {
        red[tid] = acc[e];
        __syncthreads();
        for (int s = 128; s > 0; s >>= 1) {
            if (tid < s) red[tid] += red[tid + s];
            __syncthreads();
        }
        if (tid == 0) {
            float mp = red[0] / (float)NTOK;
            float mf = (float)g_cnt[e] / (float)NTOK;
            auxs += mp * mf;
        }
        __syncthreads();
    }
    if (tid == 0) out[(size_t)NTOK * HD] = auxs * (float)NE;
}

// ---------------- launch ----------------
extern "C" void kernel_launch(void* const* d_in, const int* in_sizes, int n_in,
                              void* d_out, int out_size) {
    const float* x     = (const float*)d_in[0];
    const float* skin  = (const float*)d_in[1];
    const float* Wimg  = (const float*)d_in[2];
    const float* Wskin = (const float*)d_in[3];
    const float* W1    = (const float*)d_in[4];
    const float* b1    = (const float*)d_in[5];
    const float* W2    = (const float*)d_in[6];
    const float* b2    = (const float*)d_in[7];
    float* out = (float*)d_out;

    cudaFuncSetAttribute(k_gemm1, cudaFuncAttributeMaxDynamicSharedMemorySize, G1_SMEM);
    cudaFuncSetAttribute(k_gemm2, cudaFuncAttributeMaxDynamicSharedMemorySize, G2_SMEM);

    k_convert<<<2048, 256>>>(W1, W2);
    k_router<<<NTOK / RT, 256>>>(x, skin, Wimg, Wskin);
    k_gemm1<<<dim3(1, NTOK / 128, NE), 256, G1_SMEM>>>(b1);
    k_gemm2<<<dim3(HD / 128, NE, NTOK / 128), 256, G2_SMEM>>>(b2);
    k_combine<<<NTOK, 256>>>(x, out);
    k_aux<<<1, 256>>>(out, out_size);
}

// round 8
// speedup vs baseline: 1.1807x; 1.0693x over previous
#include <cuda_runtime.h>
#include <cuda_bf16.h>
#include <cstdint>

#define NTOK 16384
#define HD   2048
#define NE   8
#define BD   128
#define EPSF 1e-6f

// ---------------- static device scratch ----------------
__device__ __nv_bfloat16 g_xb [NTOK * HD];
__device__ __nv_bfloat16 g_w1b[NE * BD * HD];
__device__ __nv_bfloat16 g_w2b[NE * HD * BD];
__device__ __nv_bfloat16 g_scr[2 * NTOK * HD];
__device__ float g_w   [NTOK * NE];
__device__ float g_prob[NTOK * NE];
__device__ int   g_tok [NE * NTOK];
__device__ int   g_cnt [NE];

// ---------------- helpers ----------------
static __device__ __forceinline__ uint32_t smem_u32(const void* p) {
    return (uint32_t)__cvta_generic_to_shared(p);
}
#define CP16(dst_u32, src_ptr) \
    asm volatile("cp.async.cg.shared.global [%0], [%1], 16;\n" :: "r"(dst_u32), "l"(src_ptr))
#define CP_COMMIT() asm volatile("cp.async.commit_group;\n" ::)
#define CP_WAIT(n)  asm volatile("cp.async.wait_group %0;\n" :: "n"(n))

static __device__ __forceinline__ void ldm4(uint32_t& r0, uint32_t& r1, uint32_t& r2, uint32_t& r3,
                                            uint32_t addr) {
    asm volatile("ldmatrix.sync.aligned.m8n8.x4.shared.b16 {%0,%1,%2,%3}, [%4];"
                 : "=r"(r0), "=r"(r1), "=r"(r2), "=r"(r3) : "r"(addr));
}
static __device__ __forceinline__ void mma16816(float* c, const uint32_t* a, const uint32_t* b) {
    asm volatile(
        "mma.sync.aligned.m16n8k16.row.col.f32.bf16.bf16.f32 "
        "{%0,%1,%2,%3}, {%4,%5,%6,%7}, {%8,%9}, {%0,%1,%2,%3};"
        : "+f"(c[0]), "+f"(c[1]), "+f"(c[2]), "+f"(c[3])
        : "r"(a[0]), "r"(a[1]), "r"(a[2]), "r"(a[3]), "r"(b[0]), "r"(b[1]));
}

// ---------------- kernel 1: weights -> bf16 (+ counter init) ----------------
__global__ void k_convert(const float* __restrict__ W1, const float* __restrict__ W2) {
    if (blockIdx.x == 0 && threadIdx.x < NE) g_cnt[threadIdx.x] = 0;
    int total = NE * BD * HD;
    for (int i = blockIdx.x * blockDim.x + threadIdx.x; i < total; i += gridDim.x * blockDim.x) {
        g_w1b[i] = __float2bfloat16(W1[i]);
        g_w2b[i] = __float2bfloat16(W2[i]);
    }
}

// ---------------- kernel 2: router (8 tokens per block, 8 warps = 8 experts) ----------------
#define RT 8
__global__ __launch_bounds__(256) void k_router(const float* __restrict__ x,
                                                const float* __restrict__ skin,
                                                const float* __restrict__ Wimg,
                                                const float* __restrict__ Wskin) {
    int nb = blockIdx.x * RT;
    int tid = threadIdx.x, lane = tid & 31, wid = tid >> 5;

    __shared__ float lg[RT][NE];

    const float4* wr = (const float4*)(Wimg + (size_t)wid * HD);
#pragma unroll
    for (int t = 0; t < RT; t++) {
        int n = nb + t;
        const float4* xr = (const float4*)(x + (size_t)n * HD);
        float acc = 0.f;
#pragma unroll 4
        for (int j = lane; j < HD / 4; j += 32) {
            float4 a = xr[j];
            float4 b = wr[j];
            acc += a.x * b.x + a.y * b.y + a.z * b.z + a.w * b.w;
        }
#pragma unroll
        for (int o = 16; o; o >>= 1) acc += __shfl_xor_sync(0xffffffffu, acc, o);
        if (lane == 0) {
            float s = skin[n * 3 + 0] * Wskin[wid * 3 + 0] +
                      skin[n * 3 + 1] * Wskin[wid * 3 + 1] +
                      skin[n * 3 + 2] * Wskin[wid * 3 + 2];
            lg[t][wid] = acc + s;
        }
    }

    {
        const float4* xs = (const float4*)(x + (size_t)nb * HD);
        __nv_bfloat162* xd = (__nv_bfloat162*)(g_xb + (size_t)nb * HD);
        for (int i = tid; i < RT * HD / 4; i += 256) {
            float4 a = xs[i];
            __nv_bfloat162 p0, p1;
            p0.x = __float2bfloat16(a.x); p0.y = __float2bfloat16(a.y);
            p1.x = __float2bfloat16(a.z); p1.y = __float2bfloat16(a.w);
            xd[2 * i] = p0; xd[2 * i + 1] = p1;
        }
    }
    __syncthreads();

    if (tid < RT) {
        int t = tid, n = nb + t;
        float p[NE];
        float mx = lg[t][0];
#pragma unroll
        for (int e = 1; e < NE; e++) mx = fmaxf(mx, lg[t][e]);
        float ssum = 0.f;
#pragma unroll
        for (int e = 0; e < NE; e++) { p[e] = expf(lg[t][e] - mx); ssum += p[e]; }
        float inv = 1.f / ssum;
#pragma unroll
        for (int e = 0; e < NE; e++) p[e] *= inv;

        int i1 = 0;
#pragma unroll
        for (int e = 1; e < NE; e++) if (p[e] > p[i1]) i1 = e;
        int i2 = (i1 == 0) ? 1 : 0;
#pragma unroll
        for (int e = 0; e < NE; e++) { if (e != i1 && p[e] > p[i2]) i2 = e; }

        float v1 = p[i1], v2 = p[i2];
        float wn = 1.f / (v1 + v2 + EPSF);
        float wv[NE];
#pragma unroll
        for (int e = 0; e < NE; e++) wv[e] = 0.f;
        wv[i1] = v1 * wn;
        wv[i2] = v2 * wn;
#pragma unroll
        for (int e = 0; e < NE; e++) { g_w[n * NE + e] = wv[e]; g_prob[n * NE + e] = p[e]; }

        int p1 = atomicAdd(&g_cnt[i1], 1); g_tok[i1 * NTOK + p1] = n * 2 + 0;
        int p2 = atomicAdd(&g_cnt[i2], 1); g_tok[i2 * NTOK + p2] = n * 2 + 1;
    }
}

// ---------------- kernel 3: fused MoE expert (gemm1 + gemm2) ----------------
// phase1: h[128x128] = relu(Xg[128x2048] @ W1^T) + b1  -> smem
// phase2: loop 16 chunks n0: scr[.,n0:n0+128] = w * (h @ W2chunk^T + b2)
//
// smem layout (dynamic):
//   phase1: As[4][128][40] at 0      (40960 B), Bs[4][128][40] at 40960 (40960 B)
//   phase2: H[128][136]   at 0       (34816 B), W2s[2][128][136] at 34816 (69632 B)
//   b2s[2048] floats at 104448 (8192 B)  -> total 112640 B
#define FM_SMEM 112640
__global__ __launch_bounds__(256, 2) void k_moe(const float* __restrict__ b1,
                                                const float* __restrict__ b2) {
    extern __shared__ __align__(16) char sm[];
    __nv_bfloat16 (*As)[128][40] = (__nv_bfloat16 (*)[128][40])sm;
    __nv_bfloat16 (*Bs)[128][40] = (__nv_bfloat16 (*)[128][40])(sm + 40960);
    __nv_bfloat16 (*H)[136]       = (__nv_bfloat16 (*)[136])sm;
    __nv_bfloat16 (*W2s)[128][136] = (__nv_bfloat16 (*)[128][136])(sm + 34816);
    float* b2s = (float*)(sm + 104448);

    __shared__ int   vrow[128];
    __shared__ float wrow[128];

    int e = blockIdx.y;
    int cnt = g_cnt[e];
    int m0 = blockIdx.x * 128;
    if (m0 >= cnt) return;

    int tid = threadIdx.x, lane = tid & 31, wid = tid >> 5;
    int wm = wid >> 1, wn = wid & 1;

    // ---------- phase 1: h = relu(Xg @ W1^T + b1) ----------
    int rA0 = tid >> 2, rA1 = 64 + (tid >> 2), ch = tid & 3;
    int tok0 = (m0 + rA0 < cnt) ? (g_tok[e * NTOK + m0 + rA0] >> 1) : 0;
    int tok1 = (m0 + rA1 < cnt) ? (g_tok[e * NTOK + m0 + rA1] >> 1) : 0;

    float c[2][8][4];
#pragma unroll
    for (int mi = 0; mi < 2; mi++)
#pragma unroll
        for (int ni = 0; ni < 8; ni++)
#pragma unroll
            for (int q = 0; q < 4; q++) c[mi][ni][q] = 0.f;

    const int NK = HD / 32;  // 64

#define FM_LOAD(s, k0)                                                                        \
    do {                                                                                      \
        CP16(smem_u32(&As[s][rA0][ch * 8]), g_xb + (size_t)tok0 * HD + (k0) + ch * 8);        \
        CP16(smem_u32(&As[s][rA1][ch * 8]), g_xb + (size_t)tok1 * HD + (k0) + ch * 8);        \
        CP16(smem_u32(&Bs[s][rA0][ch * 8]), g_w1b + ((size_t)e * BD + rA0) * HD + (k0) + ch * 8); \
        CP16(smem_u32(&Bs[s][rA1][ch * 8]), g_w1b + ((size_t)e * BD + rA1) * HD + (k0) + ch * 8); \
    } while (0)

#pragma unroll
    for (int s = 0; s < 3; s++) { FM_LOAD(s, s * 32); CP_COMMIT(); }

    for (int it = 0; it < NK; it++) {
        CP_WAIT(2);
        __syncthreads();
        int pf = it + 3;
        if (pf < NK) FM_LOAD(pf & 3, pf * 32);
        CP_COMMIT();

        int s = it & 3;
#pragma unroll
        for (int kk = 0; kk < 2; kk++) {
            uint32_t a[2][4];
#pragma unroll
            for (int mi = 0; mi < 2; mi++) {
                uint32_t ad = smem_u32(&As[s][wm * 32 + mi * 16 + (lane & 15)][kk * 16 + ((lane >> 4) << 3)]);
                ldm4(a[mi][0], a[mi][1], a[mi][2], a[mi][3], ad);
            }
            uint32_t b[8][2];
#pragma unroll
            for (int nj = 0; nj < 4; nj++) {
                uint32_t ad = smem_u32(&Bs[s][wn * 64 + nj * 16 + (lane & 7) + ((lane >> 4) << 3)]
                                          [kk * 16 + (((lane >> 3) & 1) << 3)]);
                uint32_t r0, r1, r2, r3;
                ldm4(r0, r1, r2, r3, ad);
                b[2 * nj][0] = r0; b[2 * nj][1] = r1;
                b[2 * nj + 1][0] = r2; b[2 * nj + 1][1] = r3;
            }
#pragma unroll
            for (int mi = 0; mi < 2; mi++)
#pragma unroll
                for (int ni = 0; ni < 8; ni++) mma16816(c[mi][ni], a[mi], b[ni]);
        }
    }

    // all phase-1 cp.async groups have drained (tail groups are empty);
    // full sync before repurposing the As/Bs region
    __syncthreads();

    // start W2 chunk-0 load (region disjoint from H)
    int r = tid >> 1;
#pragma unroll
    for (int q = 0; q < 8; q++) {
        int col = ((tid & 1) * 8 + q) * 8;
        CP16(smem_u32(&W2s[0][r][col]), g_w2b + ((size_t)e * HD + r) * BD + col);
    }
    CP_COMMIT();

    // stage h into smem H (overlaps As region — safe after sync)
    const float* b1e = b1 + e * BD;
#pragma unroll
    for (int mi = 0; mi < 2; mi++) {
#pragma unroll
        for (int rr = 0; rr < 2; rr++) {
            int lr = wm * 32 + mi * 16 + (lane >> 2) + rr * 8;
#pragma unroll
            for (int ni = 0; ni < 8; ni++) {
                int col = wn * 64 + ni * 8 + (lane & 3) * 2;
                float v0 = fmaxf(c[mi][ni][rr * 2 + 0] + b1e[col], 0.f);
                float v1 = fmaxf(c[mi][ni][rr * 2 + 1] + b1e[col + 1], 0.f);
                __nv_bfloat162 pk;
                pk.x = __float2bfloat16(v0);
                pk.y = __float2bfloat16(v1);
                *(__nv_bfloat162*)(&H[lr][col]) = pk;
            }
        }
    }

    // metadata + b2 to smem
    if (tid < 128) {
        int gr = m0 + tid;
        int v = (gr < cnt) ? g_tok[e * NTOK + gr] : 0;
        vrow[tid] = v;
        wrow[tid] = (gr < cnt) ? g_w[(v >> 1) * NE + e] : 0.f;
    }
    for (int i = tid; i < HD; i += 256) b2s[i] = b2[(size_t)e * HD + i];

    int lim = cnt - m0;

    // ---------- phase 2: 16 output chunks of 128 cols ----------
    for (int ci = 0; ci < 16; ci++) {
        CP_WAIT(0);
        __syncthreads();
        if (ci < 15) {
#pragma unroll
            for (int q = 0; q < 8; q++) {
                int col = ((tid & 1) * 8 + q) * 8;
                CP16(smem_u32(&W2s[(ci + 1) & 1][r][col]),
                     g_w2b + ((size_t)e * HD + (ci + 1) * 128 + r) * BD + col);
            }
            CP_COMMIT();
        }

        int sb = ci & 1;
#pragma unroll
        for (int mi = 0; mi < 2; mi++)
#pragma unroll
            for (int ni = 0; ni < 8; ni++)
#pragma unroll
                for (int q = 0; q < 4; q++) c[mi][ni][q] = 0.f;

#pragma unroll
        for (int kk = 0; kk < 8; kk++) {
            uint32_t a[2][4];
#pragma unroll
            for (int mi = 0; mi < 2; mi++) {
                uint32_t ad = smem_u32(&H[wm * 32 + mi * 16 + (lane & 15)][kk * 16 + ((lane >> 4) << 3)]);
                ldm4(a[mi][0], a[mi][1], a[mi][2], a[mi][3], ad);
            }
            uint32_t b[8][2];
#pragma unroll
            for (int nj = 0; nj < 4; nj++) {
                uint32_t ad = smem_u32(&W2s[sb][wn * 64 + nj * 16 + (lane & 7) + ((lane >> 4) << 3)]
                                          [kk * 16 + (((lane >> 3) & 1) << 3)]);
                uint32_t r0, r1, r2, r3;
                ldm4(r0, r1, r2, r3, ad);
                b[2 * nj][0] = r0; b[2 * nj][1] = r1;
                b[2 * nj + 1][0] = r2; b[2 * nj + 1][1] = r3;
            }
#pragma unroll
            for (int mi = 0; mi < 2; mi++)
#pragma unroll
                for (int ni = 0; ni < 8; ni++) mma16816(c[mi][ni], a[mi], b[ni]);
        }

        // stage scaled output into the consumed W2 buffer
        __syncthreads();
#pragma unroll
        for (int mi = 0; mi < 2; mi++) {
#pragma unroll
            for (int rr = 0; rr < 2; rr++) {
                int lr = wm * 32 + mi * 16 + (lane >> 2) + rr * 8;
                float wv = wrow[lr];
#pragma unroll
                for (int ni = 0; ni < 8; ni++) {
                    int col = wn * 64 + ni * 8 + (lane & 3) * 2;
                    float v0 = wv * (c[mi][ni][rr * 2 + 0] + b2s[ci * 128 + col]);
                    float v1 = wv * (c[mi][ni][rr * 2 + 1] + b2s[ci * 128 + col + 1]);
                    __nv_bfloat162 pk;
                    pk.x = __float2bfloat16(v0);
                    pk.y = __float2bfloat16(v1);
                    *(__nv_bfloat162*)(&W2s[sb][lr][col]) = pk;
                }
            }
        }
        __syncthreads();

        // coalesced scatter store: 16 lanes per 256B row segment
        for (int i = tid; i < 2048; i += 256) {
            int rr2 = i >> 4, cc = (i & 15) << 3;
            if (rr2 < lim) {
                int v = vrow[rr2];
                uint4 val = *(const uint4*)(&W2s[sb][rr2][cc]);
                *(uint4*)(g_scr + (size_t)v * HD + ci * 128 + cc) = val;
            }
        }
    }
}

// ---------------- kernel 4: combine ----------------
__global__ __launch_bounds__(256) void k_combine(const float* __restrict__ x, float* __restrict__ out) {
    int n = blockIdx.x;
    int tid = threadIdx.x;
    const float4* xr = (const float4*)(x + (size_t)n * HD);
    float4* o = (float4*)(out + (size_t)n * HD);
    const __nv_bfloat162* s0 = (const __nv_bfloat162*)(g_scr + (size_t)(2 * n) * HD);
    const __nv_bfloat162* s1 = (const __nv_bfloat162*)(g_scr + (size_t)(2 * n + 1) * HD);
#pragma unroll
    for (int j = tid; j < HD / 4; j += 256) {
        float4 a = xr[j];
        __nv_bfloat162 p0 = s0[2 * j], p1 = s0[2 * j + 1];
        __nv_bfloat162 q0 = s1[2 * j], q1 = s1[2 * j + 1];
        float4 r;
        r.x = a.x + __bfloat162float(p0.x) + __bfloat162float(q0.x);
        r.y = a.y + __bfloat162float(p0.y) + __bfloat162float(q0.y);
        r.z = a.z + __bfloat162float(p1.x) + __bfloat162float(q1.x);
        r.w = a.w + __bfloat162float(p1.y) + __bfloat162float(q1.y);
        o[j] = r;
    }
}

// ---------------- kernel 5: aux loss ----------------
__global__ void k_aux(float* __restrict__ out, int out_size) {
    if (out_size <= NTOK * HD) return;
    __shared__ float red[256];
    __shared__ float auxs;
    int tid = threadIdx.x;
    if (tid == 0) auxs = 0.f;
    float acc[NE];
#pragma unroll
    for (int e = 0; e < NE; e++) acc[e] = 0.f;
    for (int n = tid; n < NTOK; n += 256) {
#pragma unroll
        for (int e = 0; e < NE; e++) acc[e] += g_prob[n * NE + e];
    }
    __syncthreads();
    for (int e = 0; e < NE; e++) {
        red[tid] = acc[e];
        __syncthreads();
        for (int s = 128; s > 0; s >>= 1) {
            if (tid < s) red[tid] += red[tid + s];
            __syncthreads();
        }
        if (tid == 0) {
            float mp = red[0] / (float)NTOK;
            float mf = (float)g_cnt[e] / (float)NTOK;
            auxs += mp * mf;
        }
        __syncthreads();
    }
    if (tid == 0) out[(size_t)NTOK * HD] = auxs * (float)NE;
}

// ---------------- launch ----------------
extern "C" void kernel_launch(void* const* d_in, const int* in_sizes, int n_in,
                              void* d_out, int out_size) {
    const float* x     = (const float*)d_in[0];
    const float* skin  = (const float*)d_in[1];
    const float* Wimg  = (const float*)d_in[2];
    const float* Wskin = (const float*)d_in[3];
    const float* W1    = (const float*)d_in[4];
    const float* b1    = (const float*)d_in[5];
    const float* W2    = (const float*)d_in[6];
    const float* b2    = (const float*)d_in[7];
    float* out = (float*)d_out;

    cudaFuncSetAttribute(k_moe, cudaFuncAttributeMaxDynamicSharedMemorySize, FM_SMEM);

    k_convert<<<2048, 256>>>(W1, W2);
    k_router<<<NTOK / RT, 256>>>(x, skin, Wimg, Wskin);
    k_moe<<<dim3(NTOK / 128, NE), 256, FM_SMEM>>>(b1, b2);
    k_combine<<<NTOK, 256>>>(x, out);
    k_aux<<<1, 256>>>(out, out_size);
}

// round 9
// speedup vs baseline: 1.1839x; 1.0027x over previous
#include <cuda_runtime.h>
#include <cuda_bf16.h>
#include <cstdint>

#define NTOK 16384
#define HD   2048
#define NE   8
#define BD   128
#define EPSF 1e-6f

// ---------------- static device scratch ----------------
__device__ __nv_bfloat16 g_xb [NTOK * HD];
__device__ __nv_bfloat16 g_w1b[NE * BD * HD];
__device__ __nv_bfloat16 g_w2b[NE * HD * BD];
__device__ __nv_bfloat16 g_scr[2 * NTOK * HD];
__device__ float g_w   [NTOK * NE];
__device__ float g_pp  [(NTOK / 8) * NE];   // per-router-block prob partial sums
__device__ int   g_tok [NE * NTOK];
__device__ int   g_cnt [NE];

// ---------------- helpers ----------------
static __device__ __forceinline__ uint32_t smem_u32(const void* p) {
    return (uint32_t)__cvta_generic_to_shared(p);
}
#define CP16(dst_u32, src_ptr) \
    asm volatile("cp.async.cg.shared.global [%0], [%1], 16;\n" :: "r"(dst_u32), "l"(src_ptr))
#define CP_COMMIT() asm volatile("cp.async.commit_group;\n" ::)
#define CP_WAIT(n)  asm volatile("cp.async.wait_group %0;\n" :: "n"(n))

static __device__ __forceinline__ void ldm4(uint32_t& r0, uint32_t& r1, uint32_t& r2, uint32_t& r3,
                                            uint32_t addr) {
    asm volatile("ldmatrix.sync.aligned.m8n8.x4.shared.b16 {%0,%1,%2,%3}, [%4];"
                 : "=r"(r0), "=r"(r1), "=r"(r2), "=r"(r3) : "r"(addr));
}
static __device__ __forceinline__ void mma16816(float* c, const uint32_t* a, const uint32_t* b) {
    asm volatile(
        "mma.sync.aligned.m16n8k16.row.col.f32.bf16.bf16.f32 "
        "{%0,%1,%2,%3}, {%4,%5,%6,%7}, {%8,%9}, {%0,%1,%2,%3};"
        : "+f"(c[0]), "+f"(c[1]), "+f"(c[2]), "+f"(c[3])
        : "r"(a[0]), "r"(a[1]), "r"(a[2]), "r"(a[3]), "r"(b[0]), "r"(b[1]));
}

// ---------------- kernel 1: weights -> bf16 (+ counter init) ----------------
__global__ void k_convert(const float* __restrict__ W1, const float* __restrict__ W2) {
    if (blockIdx.x == 0 && threadIdx.x < NE) g_cnt[threadIdx.x] = 0;
    int total = NE * BD * HD;
    for (int i = blockIdx.x * blockDim.x + threadIdx.x; i < total; i += gridDim.x * blockDim.x) {
        g_w1b[i] = __float2bfloat16(W1[i]);
        g_w2b[i] = __float2bfloat16(W2[i]);
    }
}

// ---------------- kernel 2: router v2 (8 tokens/block; W_img chunk in registers) ----------------
#define RT 8
__global__ __launch_bounds__(256) void k_router(const float* __restrict__ x,
                                                const float* __restrict__ skin,
                                                const float* __restrict__ Wimg,
                                                const float* __restrict__ Wskin) {
    int nb = blockIdx.x * RT;
    int tid = threadIdx.x, lane = tid & 31, wid = tid >> 5;

    __shared__ float part[8][RT][NE];
    __shared__ float lg[RT][NE];
    __shared__ float sp[RT][NE];

    // 1) bf16 conversion pass (coalesced DRAM read; populates L1 for the dot pass)
    {
        const float4* xs4 = (const float4*)(x + (size_t)nb * HD);
        __nv_bfloat162* xd = (__nv_bfloat162*)(g_xb + (size_t)nb * HD);
        for (int i = tid; i < RT * HD / 4; i += 256) {
            float4 a = xs4[i];
            __nv_bfloat162 p0, p1;
            p0.x = __float2bfloat16(a.x); p0.y = __float2bfloat16(a.y);
            p1.x = __float2bfloat16(a.z); p1.y = __float2bfloat16(a.w);
            xd[2 * i] = p0; xd[2 * i + 1] = p1;
        }
    }

    // 2) load this warp's W_img chunk into registers: 8 experts x 8 cols per lane
    int base = wid * 256 + lane * 8;
    float4 wreg[NE][2];
#pragma unroll
    for (int e = 0; e < NE; e++) {
        wreg[e][0] = *(const float4*)(Wimg + (size_t)e * HD + base);
        wreg[e][1] = *(const float4*)(Wimg + (size_t)e * HD + base + 4);
    }

    // 3) per-token: all 8 expert dots from one x read
    for (int t = 0; t < RT; t++) {
        const float* xr = x + (size_t)(nb + t) * HD + base;
        float4 a0 = *(const float4*)xr;
        float4 a1 = *(const float4*)(xr + 4);
        float acc[NE];
#pragma unroll
        for (int e = 0; e < NE; e++) {
            acc[e] = a0.x * wreg[e][0].x + a0.y * wreg[e][0].y +
                     a0.z * wreg[e][0].z + a0.w * wreg[e][0].w +
                     a1.x * wreg[e][1].x + a1.y * wreg[e][1].y +
                     a1.z * wreg[e][1].z + a1.w * wreg[e][1].w;
        }
#pragma unroll
        for (int o = 16; o; o >>= 1)
#pragma unroll
            for (int e = 0; e < NE; e++) acc[e] += __shfl_xor_sync(0xffffffffu, acc[e], o);
#pragma unroll
        for (int e = 0; e < NE; e++)
            if (lane == e) part[wid][t][e] = acc[e];
    }
    __syncthreads();

    // 4) cross-warp combine + skin term
    if (tid < RT * NE) {
        int t = tid >> 3, e = tid & 7;
        float s = 0.f;
#pragma unroll
        for (int w = 0; w < 8; w++) s += part[w][t][e];
        int n = nb + t;
        s += skin[n * 3 + 0] * Wskin[e * 3 + 0] +
             skin[n * 3 + 1] * Wskin[e * 3 + 1] +
             skin[n * 3 + 2] * Wskin[e * 3 + 2];
        lg[t][e] = s;
    }
    __syncthreads();

    // 5) softmax + top-2 per token
    if (tid < RT) {
        int t = tid, n = nb + t;
        float p[NE];
        float mx = lg[t][0];
#pragma unroll
        for (int e = 1; e < NE; e++) mx = fmaxf(mx, lg[t][e]);
        float ssum = 0.f;
#pragma unroll
        for (int e = 0; e < NE; e++) { p[e] = expf(lg[t][e] - mx); ssum += p[e]; }
        float inv = 1.f / ssum;
#pragma unroll
        for (int e = 0; e < NE; e++) p[e] *= inv;

        int i1 = 0;
#pragma unroll
        for (int e = 1; e < NE; e++) if (p[e] > p[i1]) i1 = e;
        int i2 = (i1 == 0) ? 1 : 0;
#pragma unroll
        for (int e = 0; e < NE; e++) { if (e != i1 && p[e] > p[i2]) i2 = e; }

        float v1 = p[i1], v2 = p[i2];
        float wn = 1.f / (v1 + v2 + EPSF);
        float wv[NE];
#pragma unroll
        for (int e = 0; e < NE; e++) wv[e] = 0.f;
        wv[i1] = v1 * wn;
        wv[i2] = v2 * wn;
#pragma unroll
        for (int e = 0; e < NE; e++) { g_w[n * NE + e] = wv[e]; sp[t][e] = p[e]; }

        int p1 = atomicAdd(&g_cnt[i1], 1); g_tok[i1 * NTOK + p1] = n * 2 + 0;
        int p2 = atomicAdd(&g_cnt[i2], 1); g_tok[i2 * NTOK + p2] = n * 2 + 1;
    }
    __syncthreads();

    // 6) per-block prob partials for aux loss (deterministic)
    if (tid < NE) {
        float s = 0.f;
#pragma unroll
        for (int t = 0; t < RT; t++) s += sp[t][tid];
        g_pp[blockIdx.x * NE + tid] = s;
    }
}

// ---------------- kernel 3: fused MoE expert (gemm1 + gemm2) ----------------
#define FM_SMEM 112640
__global__ __launch_bounds__(256, 2) void k_moe(const float* __restrict__ b1,
                                                const float* __restrict__ b2) {
    extern __shared__ __align__(16) char sm[];
    __nv_bfloat16 (*As)[128][40] = (__nv_bfloat16 (*)[128][40])sm;
    __nv_bfloat16 (*Bs)[128][40] = (__nv_bfloat16 (*)[128][40])(sm + 40960);
    __nv_bfloat16 (*H)[136]       = (__nv_bfloat16 (*)[136])sm;
    __nv_bfloat16 (*W2s)[128][136] = (__nv_bfloat16 (*)[128][136])(sm + 34816);
    float* b2s = (float*)(sm + 104448);

    __shared__ int   vrow[128];
    __shared__ float wrow[128];

    int e = blockIdx.y;
    int cnt = g_cnt[e];
    int m0 = blockIdx.x * 128;
    if (m0 >= cnt) return;

    int tid = threadIdx.x, lane = tid & 31, wid = tid >> 5;
    int wm = wid >> 1, wn = wid & 1;

    // ---------- phase 1 ----------
    int rA0 = tid >> 2, rA1 = 64 + (tid >> 2), ch = tid & 3;
    int tok0 = (m0 + rA0 < cnt) ? (g_tok[e * NTOK + m0 + rA0] >> 1) : 0;
    int tok1 = (m0 + rA1 < cnt) ? (g_tok[e * NTOK + m0 + rA1] >> 1) : 0;

    float c[2][8][4];
#pragma unroll
    for (int mi = 0; mi < 2; mi++)
#pragma unroll
        for (int ni = 0; ni < 8; ni++)
#pragma unroll
            for (int q = 0; q < 4; q++) c[mi][ni][q] = 0.f;

    const int NK = HD / 32;  // 64

#define FM_LOAD(s, k0)                                                                        \
    do {                                                                                      \
        CP16(smem_u32(&As[s][rA0][ch * 8]), g_xb + (size_t)tok0 * HD + (k0) + ch * 8);        \
        CP16(smem_u32(&As[s][rA1][ch * 8]), g_xb + (size_t)tok1 * HD + (k0) + ch * 8);        \
        CP16(smem_u32(&Bs[s][rA0][ch * 8]), g_w1b + ((size_t)e * BD + rA0) * HD + (k0) + ch * 8); \
        CP16(smem_u32(&Bs[s][rA1][ch * 8]), g_w1b + ((size_t)e * BD + rA1) * HD + (k0) + ch * 8); \
    } while (0)

#pragma unroll
    for (int s = 0; s < 3; s++) { FM_LOAD(s, s * 32); CP_COMMIT(); }

    for (int it = 0; it < NK; it++) {
        CP_WAIT(2);
        __syncthreads();
        int pf = it + 3;
        if (pf < NK) FM_LOAD(pf & 3, pf * 32);
        CP_COMMIT();

        int s = it & 3;
#pragma unroll
        for (int kk = 0; kk < 2; kk++) {
            uint32_t a[2][4];
#pragma unroll
            for (int mi = 0; mi < 2; mi++) {
                uint32_t ad = smem_u32(&As[s][wm * 32 + mi * 16 + (lane & 15)][kk * 16 + ((lane >> 4) << 3)]);
                ldm4(a[mi][0], a[mi][1], a[mi][2], a[mi][3], ad);
            }
            uint32_t b[8][2];
#pragma unroll
            for (int nj = 0; nj < 4; nj++) {
                uint32_t ad = smem_u32(&Bs[s][wn * 64 + nj * 16 + (lane & 7) + ((lane >> 4) << 3)]
                                          [kk * 16 + (((lane >> 3) & 1) << 3)]);
                uint32_t r0, r1, r2, r3;
                ldm4(r0, r1, r2, r3, ad);
                b[2 * nj][0] = r0; b[2 * nj][1] = r1;
                b[2 * nj + 1][0] = r2; b[2 * nj + 1][1] = r3;
            }
#pragma unroll
            for (int mi = 0; mi < 2; mi++)
#pragma unroll
                for (int ni = 0; ni < 8; ni++) mma16816(c[mi][ni], a[mi], b[ni]);
        }
    }

    __syncthreads();

    // start W2 chunk-0 load
    int r = tid >> 1;
#pragma unroll
    for (int q = 0; q < 8; q++) {
        int col = ((tid & 1) * 8 + q) * 8;
        CP16(smem_u32(&W2s[0][r][col]), g_w2b + ((size_t)e * HD + r) * BD + col);
    }
    CP_COMMIT();

    // stage h into smem H
    const float* b1e = b1 + e * BD;
#pragma unroll
    for (int mi = 0; mi < 2; mi++) {
#pragma unroll
        for (int rr = 0; rr < 2; rr++) {
            int lr = wm * 32 + mi * 16 + (lane >> 2) + rr * 8;
#pragma unroll
            for (int ni = 0; ni < 8; ni++) {
                int col = wn * 64 + ni * 8 + (lane & 3) * 2;
                float v0 = fmaxf(c[mi][ni][rr * 2 + 0] + b1e[col], 0.f);
                float v1 = fmaxf(c[mi][ni][rr * 2 + 1] + b1e[col + 1], 0.f);
                __nv_bfloat162 pk;
                pk.x = __float2bfloat16(v0);
                pk.y = __float2bfloat16(v1);
                *(__nv_bfloat162*)(&H[lr][col]) = pk;
            }
        }
    }

    if (tid < 128) {
        int gr = m0 + tid;
        int v = (gr < cnt) ? g_tok[e * NTOK + gr] : 0;
        vrow[tid] = v;
        wrow[tid] = (gr < cnt) ? g_w[(v >> 1) * NE + e] : 0.f;
    }
    for (int i = tid; i < HD; i += 256) b2s[i] = b2[(size_t)e * HD + i];

    int lim = cnt - m0;

    // ---------- phase 2 ----------
    for (int ci = 0; ci < 16; ci++) {
        CP_WAIT(0);
        __syncthreads();
        if (ci < 15) {
#pragma unroll
            for (int q = 0; q < 8; q++) {
                int col = ((tid & 1) * 8 + q) * 8;
                CP16(smem_u32(&W2s[(ci + 1) & 1][r][col]),
                     g_w2b + ((size_t)e * HD + (ci + 1) * 128 + r) * BD + col);
            }
            CP_COMMIT();
        }

        int sb = ci & 1;
#pragma unroll
        for (int mi = 0; mi < 2; mi++)
#pragma unroll
            for (int ni = 0; ni < 8; ni++)
#pragma unroll
                for (int q = 0; q < 4; q++) c[mi][ni][q] = 0.f;

#pragma unroll
        for (int kk = 0; kk < 8; kk++) {
            uint32_t a[2][4];
#pragma unroll
            for (int mi = 0; mi < 2; mi++) {
                uint32_t ad = smem_u32(&H[wm * 32 + mi * 16 + (lane & 15)][kk * 16 + ((lane >> 4) << 3)]);
                ldm4(a[mi][0], a[mi][1], a[mi][2], a[mi][3], ad);
            }
            uint32_t b[8][2];
#pragma unroll
            for (int nj = 0; nj < 4; nj++) {
                uint32_t ad = smem_u32(&W2s[sb][wn * 64 + nj * 16 + (lane & 7) + ((lane >> 4) << 3)]
                                          [kk * 16 + (((lane >> 3) & 1) << 3)]);
                uint32_t r0, r1, r2, r3;
                ldm4(r0, r1, r2, r3, ad);
                b[2 * nj][0] = r0; b[2 * nj][1] = r1;
                b[2 * nj + 1][0] = r2; b[2 * nj + 1][1] = r3;
            }
#pragma unroll
            for (int mi = 0; mi < 2; mi++)
#pragma unroll
                for (int ni = 0; ni < 8; ni++) mma16816(c[mi][ni], a[mi], b[ni]);
        }

        __syncthreads();
#pragma unroll
        for (int mi = 0; mi < 2; mi++) {
#pragma unroll
            for (int rr = 0; rr < 2; rr++) {
                int lr = wm * 32 + mi * 16 + (lane >> 2) + rr * 8;
                float wv = wrow[lr];
#pragma unroll
                for (int ni = 0; ni < 8; ni++) {
                    int col = wn * 64 + ni * 8 + (lane & 3) * 2;
                    float v0 = wv * (c[mi][ni][rr * 2 + 0] + b2s[ci * 128 + col]);
                    float v1 = wv * (c[mi][ni][rr * 2 + 1] + b2s[ci * 128 + col + 1]);
                    __nv_bfloat162 pk;
                    pk.x = __float2bfloat16(v0);
                    pk.y = __float2bfloat16(v1);
                    *(__nv_bfloat162*)(&W2s[sb][lr][col]) = pk;
                }
            }
        }
        __syncthreads();

        for (int i = tid; i < 2048; i += 256) {
            int rr2 = i >> 4, cc = (i & 15) << 3;
            if (rr2 < lim) {
                int v = vrow[rr2];
                uint4 val = *(const uint4*)(&W2s[sb][rr2][cc]);
                *(uint4*)(g_scr + (size_t)v * HD + ci * 128 + cc) = val;
            }
        }
    }
}

// ---------------- kernel 4: combine ----------------
__global__ __launch_bounds__(256) void k_combine(const float* __restrict__ x, float* __restrict__ out) {
    int n = blockIdx.x;
    int tid = threadIdx.x;
    const float4* xr = (const float4*)(x + (size_t)n * HD);
    float4* o = (float4*)(out + (size_t)n * HD);
    const __nv_bfloat162* s0 = (const __nv_bfloat162*)(g_scr + (size_t)(2 * n) * HD);
    const __nv_bfloat162* s1 = (const __nv_bfloat162*)(g_scr + (size_t)(2 * n + 1) * HD);
#pragma unroll
    for (int j = tid; j < HD / 4; j += 256) {
        float4 a = xr[j];
        __nv_bfloat162 p0 = s0[2 * j], p1 = s0[2 * j + 1];
        __nv_bfloat162 q0 = s1[2 * j], q1 = s1[2 * j + 1];
        float4 r;
        r.x = a.x + __bfloat162float(p0.x) + __bfloat162float(q0.x);
        r.y = a.y + __bfloat162float(p0.y) + __bfloat162float(q0.y);
        r.z = a.z + __bfloat162float(p1.x) + __bfloat162float(q1.x);
        r.w = a.w + __bfloat162float(p1.y) + __bfloat162float(q1.y);
        o[j] = r;
    }
}

// ---------------- kernel 5: aux loss (partials reduce) ----------------
__global__ void k_aux(float* __restrict__ out, int out_size) {
    if (out_size <= NTOK * HD) return;
    __shared__ float red[256];
    __shared__ float auxs;
    int tid = threadIdx.x;
    if (tid == 0) auxs = 0.f;
    float acc[NE];
#pragma unroll
    for (int e = 0; e < NE; e++) acc[e] = 0.f;
    for (int i = tid; i < NTOK / RT; i += 256) {
#pragma unroll
        for (int e = 0; e < NE; e++) acc[e] += g_pp[i * NE + e];
    }
    __syncthreads();
    for (int e = 0; e < NE; e++) {
        red[tid] = acc[e];
        __syncthreads();
        for (int s = 128; s > 0; s >>= 1) {
            if (tid < s) red[tid] += red[tid + s];
            __syncthreads();
        }
        if (tid == 0) {
            float mp = red[0] / (float)NTOK;
            float mf = (float)g_cnt[e] / (float)NTOK;
            auxs += mp * mf;
        }
        __syncthreads();
    }
    if (tid == 0) out[(size_t)NTOK * HD] = auxs * (float)NE;
}

// ---------------- launch ----------------
extern "C" void kernel_launch(void* const* d_in, const int* in_sizes, int n_in,
                              void* d_out, int out_size) {
    const float* x     = (const float*)d_in[0];
    const float* skin  = (const float*)d_in[1];
    const float* Wimg  = (const float*)d_in[2];
    const float* Wskin = (const float*)d_in[3];
    const float* W1    = (const float*)d_in[4];
    const float* b1    = (const float*)d_in[5];
    const float* W2    = (const float*)d_in[6];
    const float* b2    = (const float*)d_in[7];
    float* out = (float*)d_out;

    cudaFuncSetAttribute(k_moe, cudaFuncAttributeMaxDynamicSharedMemorySize, FM_SMEM);

    k_convert<<<2048, 256>>>(W1, W2);
    k_router<<<NTOK / RT, 256>>>(x, skin, Wimg, Wskin);
    k_moe<<<dim3(NTOK / 128, NE), 256, FM_SMEM>>>(b1, b2);
    k_combine<<<NTOK, 256>>>(x, out);
    k_aux<<<1, 256>>>(out, out_size);
}